// round 4
// baseline (speedup 1.0000x reference)
#include <cuda_runtime.h>

// IndRNN, 2 layers fused: per channel c=(b,h):
//   s0 = relu(x[t,c] + w0[h]*s0);  s1 = relu(s0 + w1[h]*s1);  out[t,c] = s1
// One thread per channel. Triple-buffered, prefetch distance 2 chunks:
// during each compute phase, 32 LDGs per warp are in flight (2 MB chip-wide).

#define T_STEPS 2048
#define BATCH   32
#define HID     512
#define CHAN    (BATCH * HID)   // 16384
#define U       16              // time steps per chunk
#define NCHUNK  (T_STEPS / U)   // 128

__global__ __launch_bounds__(32) void indrnn_fused_kernel(
    const float* __restrict__ x,      // [T, B, H]
    const float* __restrict__ w_hh,   // [2, H]
    const float* __restrict__ h0,     // [2, B, H]
    float* __restrict__ out)          // [T, B, H]
{
    const int c = blockIdx.x * 32 + threadIdx.x;   // channel in [0, 16384)
    const int h = c & (HID - 1);

    const float w0 = w_hh[h];
    const float w1 = w_hh[HID + h];
    float s0 = h0[c];
    float s1 = h0[CHAN + c];

    const float* xp = x + c;
    float*       op = out + c;

    float b0[U], b1[U], b2[U];

#define PREF(buf, chunk)                                                   \
    _Pragma("unroll")                                                      \
    for (int u = 0; u < U; ++u)                                            \
        buf[u] = __ldcs(xp + (size_t)((chunk) * U + u) * CHAN);

#define COMP(buf, chunk)                                                   \
    _Pragma("unroll")                                                      \
    for (int u = 0; u < U; ++u) {                                          \
        s0 = fmaxf(fmaf(s0, w0, buf[u]), 0.0f);                            \
        s1 = fmaxf(fmaf(s1, w1, s0), 0.0f);                                \
        __stcs(op + (size_t)((chunk) * U + u) * CHAN, s1);                 \
    }

    // Prologue: chunks 0 and 1 in flight.
    PREF(b0, 0);
    PREF(b1, 1);

    // Main loop: 42 iterations x 3 chunks = chunks 0..125 computed,
    // prefetch always 2 chunks ahead (max prefetched chunk index = 127).
#pragma unroll 1
    for (int j = 0; j < (NCHUNK - 2) / 3; ++j) {
        const int c3 = 3 * j;
        PREF(b2, c3 + 2);  COMP(b0, c3);
        PREF(b0, c3 + 3);  COMP(b1, c3 + 1);
        PREF(b1, c3 + 4);  COMP(b2, c3 + 2);
    }

    // Epilogue: chunks 126, 127 already resident in b0, b1.
    COMP(b0, NCHUNK - 2);
    COMP(b1, NCHUNK - 1);

#undef PREF
#undef COMP
}

extern "C" void kernel_launch(void* const* d_in, const int* in_sizes, int n_in,
                              void* d_out, int out_size)
{
    const float* x    = (const float*)d_in[0];  // [2048, 32, 512]
    const float* w_hh = (const float*)d_in[1];  // [2, 512]
    const float* h0   = (const float*)d_in[2];  // [2, 32, 512]
    float*       out  = (float*)d_out;          // [2048, 32, 512]

    (void)in_sizes; (void)n_in; (void)out_size;

    // 16384 channels / 32 threads = 512 single-warp blocks.
    indrnn_fused_kernel<<<512, 32>>>(x, w_hh, h0, out);
}

// round 7
// speedup vs baseline: 1.5860x; 1.5860x over previous
#include <cuda_runtime.h>
#include <cstdint>

// IndRNN, 2 layers fused, cp.async smem pipeline.
// Per channel c=(b,h): s0 = relu(x[t,c] + w0*s0); s1 = relu(s0 + w1*s1); out[t,c]=s1
// Block = 1 warp = 32 channels. x is streamed through a 16-stage smem ring
// with cp.async (prefetch distance 12 chunks -> ~24KB in flight per warp,
// ~12MB chip-wide), decoupling memory-level parallelism from registers.

#define T_STEPS 2048
#define BATCH   32
#define HID     512
#define CHAN    (BATCH * HID)     // 16384
#define U       16                // time steps per chunk
#define NCHUNK  (T_STEPS / U)     // 128
#define NSTAGE  16                // smem ring stages (power of 2)
#define DEPTH   12                // prefetch distance in chunks (< NSTAGE)

__device__ __forceinline__ uint32_t smem_u32(const void* p) {
    return (uint32_t)__cvta_generic_to_shared(p);
}

__global__ __launch_bounds__(32) void indrnn_cpasync_kernel(
    const float* __restrict__ x,      // [T, B, H]
    const float* __restrict__ w_hh,   // [2, H]
    const float* __restrict__ h0,     // [2, B, H]
    float* __restrict__ out)          // [T, B, H]
{
    __shared__ float ring[NSTAGE][U * 32];   // 32 KB

    const int lane = threadIdx.x;
    const int c    = blockIdx.x * 32 + lane;   // channel
    const int h    = c & (HID - 1);

    const float w0 = w_hh[h];
    const float w1 = w_hh[HID + h];
    float s0 = h0[c];
    float s1 = h0[CHAN + c];

    const float* xbase = x + blockIdx.x * 32;  // this block's 32-channel column
    float*       op    = out + c;

    // cp.async assignment: 4 ops per thread per chunk; each op moves 16B.
    // op q covers steps q*4 .. q*4+3; thread's (sub,col) picks (step, 16B slice).
    const int sub = lane >> 3;        // 0..3 -> step within the 4-step group
    const int col = (lane & 7) * 4;   // float offset within the 32-float row

#define ISSUE_CHUNK(k)                                                        \
    do {                                                                      \
        const int   _stage = (k) & (NSTAGE - 1);                              \
        const float* _src0 = xbase + (size_t)((k) * U) * CHAN;                \
        _Pragma("unroll")                                                     \
        for (int q = 0; q < 4; ++q) {                                         \
            const int    _step = q * 4 + sub;                                 \
            const float* _src  = _src0 + (size_t)_step * CHAN + col;          \
            uint32_t _dst = smem_u32(&ring[_stage][_step * 32 + col]);        \
            asm volatile("cp.async.cg.shared.global [%0], [%1], 16;\n"        \
                         :: "r"(_dst), "l"(_src));                            \
        }                                                                     \
        asm volatile("cp.async.commit_group;\n" ::: "memory");                \
    } while (0)

    // Prologue: fill the pipeline DEPTH chunks deep.
#pragma unroll
    for (int k = 0; k < DEPTH; ++k)
        ISSUE_CHUNK(k);

#pragma unroll 1
    for (int k = 0; k < NCHUNK; ++k) {
        if (k + DEPTH < NCHUNK) {
            ISSUE_CHUNK(k + DEPTH);
        } else {
            // Empty group keeps the pending-group count arithmetic constant
            // so the immediate in wait_group stays valid in the tail.
            asm volatile("cp.async.commit_group;\n" ::: "memory");
        }

        // All groups except the newest DEPTH are complete -> chunk k is in smem.
        asm volatile("cp.async.wait_group %0;\n" :: "n"(DEPTH) : "memory");
        __syncwarp();

        const int stage = k & (NSTAGE - 1);
#pragma unroll
        for (int s = 0; s < U; ++s) {
            const float xv = ring[stage][s * 32 + lane];
            s0 = fmaxf(fmaf(s0, w0, xv), 0.0f);
            s1 = fmaxf(fmaf(s1, w1, s0), 0.0f);
            __stcs(op + (size_t)(k * U + s) * CHAN, s1);
        }
    }
#undef ISSUE_CHUNK
}

extern "C" void kernel_launch(void* const* d_in, const int* in_sizes, int n_in,
                              void* d_out, int out_size)
{
    const float* x    = (const float*)d_in[0];  // [2048, 32, 512]
    const float* w_hh = (const float*)d_in[1];  // [2, 512]
    const float* h0   = (const float*)d_in[2];  // [2, 32, 512]
    float*       out  = (float*)d_out;          // [2048, 32, 512]

    (void)in_sizes; (void)n_in; (void)out_size;

    indrnn_cpasync_kernel<<<512, 32>>>(x, w_hh, h0, out);
}